// round 3
// baseline (speedup 1.0000x reference)
#include <cuda_runtime.h>
#include <math.h>

#define SEQ   128
#define BATCH 512
#define INDIM 128
#define HID   128
#define FULLM 0xffffffffu

// One block per batch element, 128 threads (4 warps). Warp g simulates the
// 8-qubit circuit for gate-type g (f,i,g,o). Thread owns 8 complex amplitudes
// of the 256-dim statevector: index i = r*32 + lane (r = 0..7 register slot).
// Index bit k corresponds to wire (7-k).
__global__ __launch_bounds__(128, 4)
void qlstm_kernel(const float* __restrict__ inputs,
                  const float* __restrict__ Wq,  const float* __restrict__ bq,
                  const float* __restrict__ pf,  const float* __restrict__ pi_,
                  const float* __restrict__ pg,  const float* __restrict__ po,
                  const float* __restrict__ Wf,  const float* __restrict__ bf,
                  const float* __restrict__ Wi,  const float* __restrict__ bi,
                  const float* __restrict__ Wg,  const float* __restrict__ bg,
                  const float* __restrict__ Wo,  const float* __restrict__ bo,
                  float* __restrict__ out)
{
    __shared__ float sWq[8][256];      // rows 0..7 of Wq (only ones used!)
    __shared__ float sWT[4][8][128];   // gate weights, transposed [w][hid]
    __shared__ float sb[4][128];       // gate biases
    __shared__ float sbq[8];
    __shared__ float rc[4][2][8], rs[4][2][8];  // RY half-angle cos/sin
    __shared__ float comb[256];        // [ x_t | h ]
    __shared__ float cst[128];         // cell state
    __shared__ float cth[8], sth[8];   // RX half-angle cos/sin (shared by all 4 gates)
    __shared__ float zz[4][8];         // <Z_w> per gate type

    const int tid  = threadIdx.x;
    const int lane = tid & 31;
    const int wp   = tid >> 5;         // warp id 0..3 == gate type
    const int b    = blockIdx.x;

    // ---- stage weights to smem ----
    for (int i = tid; i < 8 * 256; i += 128) sWq[i >> 8][i & 255] = Wq[i];
    {
        const float* Wg4[4] = {Wf, Wi, Wg, Wo};
        const float* bg4[4] = {bf, bi, bg, bo};
        const float* pp4[4] = {pf, pi_, pg, po};
        for (int g = 0; g < 4; g++) {
            for (int i = tid; i < 128 * 8; i += 128) {
                int hd = i >> 3, w = i & 7;
                sWT[g][w][hd] = Wg4[g][hd * 8 + w];
            }
            sb[g][tid] = bg4[g][tid];
            if (tid < 16) {
                float a = 0.5f * pp4[g][tid];
                rc[g][tid >> 3][tid & 7] = cosf(a);
                rs[g][tid >> 3][tid & 7] = sinf(a);
            }
        }
    }
    if (tid < 8) sbq[tid] = bq[tid];
    comb[128 + tid] = 0.f;   // h0 = 0
    cst[tid] = 0.f;          // c0 = 0
    __syncthreads();

    for (int t = 0; t < SEQ; t++) {
        // ---- phase A: load x_t (coalesced, contiguous 128 floats) ----
        comb[tid] = inputs[(t * BATCH + b) * INDIM + tid];
        __syncthreads();

        // ---- phase B: q_in rows 0..7 (warp wp computes rows 2wp, 2wp+1) ----
        #pragma unroll
        for (int rr = 0; rr < 2; rr++) {
            int row = wp * 2 + rr;
            float sum = 0.f;
            #pragma unroll
            for (int k = 0; k < 8; k++)
                sum = fmaf(sWq[row][lane + 32 * k], comb[lane + 32 * k], sum);
            #pragma unroll
            for (int off = 16; off; off >>= 1)
                sum += __shfl_xor_sync(FULLM, sum, off);
            if (lane == 0) {
                float a = 0.5f * (sum + sbq[row]);
                float s, c;
                sincosf(a, &s, &c);
                cth[row] = c; sth[row] = s;
            }
        }
        __syncthreads();

        // ---- phase C: statevector sim, one warp per gate type ----
        {
            const int g = wp;
            float re[8], im[8];

            // psi0 = product state from RX encoding: amp(i) = (-i)^popc(i) * prod
            float lanep = 1.f;
            #pragma unroll
            for (int k = 0; k < 5; k++)
                lanep *= ((lane >> k) & 1) ? sth[7 - k] : cth[7 - k];
            const int lpc = __popc(lane);
            #pragma unroll
            for (int r = 0; r < 8; r++) {
                float mag = lanep;
                #pragma unroll
                for (int k = 0; k < 3; k++)
                    mag *= ((r >> k) & 1) ? sth[2 - k] : cth[2 - k];
                int kk = (lpc + __popc(r)) & 3;
                re[r] = (kk == 0) ? mag : ((kk == 2) ? -mag : 0.f);
                im[r] = (kk == 1) ? -mag : ((kk == 3) ? mag : 0.f);
            }

            // DEPTH=2 x (RY layer + CNOT chain)
            #pragma unroll
            for (int d = 0; d < 2; d++) {
                #pragma unroll
                for (int w = 0; w < 8; w++) {
                    const float c = rc[g][d][w], s = rs[g][d][w];
                    if (w <= 2) {
                        // register-bit gate (index bit 7-w -> r bit 2-w)
                        const int rb = 2 - w;
                        #pragma unroll
                        for (int r0 = 0; r0 < 8; r0++) {
                            if (!((r0 >> rb) & 1)) {
                                const int r1 = r0 | (1 << rb);
                                float a0 = re[r0], a1 = re[r1];
                                re[r0] = fmaf(c, a0, -s * a1);
                                re[r1] = fmaf(s, a0,  c * a1);
                                a0 = im[r0]; a1 = im[r1];
                                im[r0] = fmaf(c, a0, -s * a1);
                                im[r1] = fmaf(s, a0,  c * a1);
                            }
                        }
                    } else {
                        // lane-bit gate via shfl_xor
                        const int pb = 7 - w;
                        const int m = 1 << pb;
                        const float sg = ((lane >> pb) & 1) ? s : -s;
                        #pragma unroll
                        for (int r = 0; r < 8; r++) {
                            float pr = __shfl_xor_sync(FULLM, re[r], m);
                            float pm = __shfl_xor_sync(FULLM, im[r], m);
                            re[r] = fmaf(c, re[r], sg * pr);
                            im[r] = fmaf(c, im[r], sg * pm);
                        }
                    }
                }
                // CNOT ladder == permutation new[i] = old[i ^ (i>>1)].
                // Materialize after layer 0; fold into measurement after layer 1.
                if (d == 0) {
                    float nre[8], nim[8];
                    const int bsl = lane ^ (lane >> 1);
                    #pragma unroll
                    for (int r = 0; r < 8; r++) {
                        const int srcR = r ^ (r >> 1);
                        const int sl = bsl ^ ((r & 1) << 4);
                        nre[r] = __shfl_sync(FULLM, re[srcR], sl);
                        nim[r] = __shfl_sync(FULLM, im[srcR], sl);
                    }
                    #pragma unroll
                    for (int r = 0; r < 8; r++) { re[r] = nre[r]; im[r] = nim[r]; }
                }
            }

            // measurement: <Z_w> with chain-2 folded into signs:
            // sign at pre-permutation index j is (-1)^parity(j >> (7-w))
            float p[8];
            #pragma unroll
            for (int r = 0; r < 8; r++)
                p[r] = re[r] * re[r] + im[r] * im[r];
            float acc[8];
            #pragma unroll
            for (int w = 0; w < 8; w++) {
                const int pb = 7 - w;
                float a = 0.f;
                if (w <= 2) {
                    #pragma unroll
                    for (int r = 0; r < 8; r++) {
                        int par = __popc(r >> (pb - 5)) & 1;
                        a += par ? -p[r] : p[r];
                    }
                } else {
                    const int lpar = __popc(lane >> pb) & 1;
                    #pragma unroll
                    for (int r = 0; r < 8; r++) {
                        int par = (__popc(r) & 1) ^ lpar;
                        a += par ? -p[r] : p[r];
                    }
                }
                acc[w] = a;
            }
            #pragma unroll
            for (int off = 16; off; off >>= 1) {
                #pragma unroll
                for (int w = 0; w < 8; w++)
                    acc[w] += __shfl_xor_sync(FULLM, acc[w], off);
            }
            if (lane == 0) {
                #pragma unroll
                for (int w = 0; w < 8; w++) zz[g][w] = acc[w];
            }
        }
        __syncthreads();

        // ---- phase D: gate GEMVs + LSTM pointwise, thread = hidden unit ----
        {
            const int hd = tid;
            float zf = sb[0][hd], zi = sb[1][hd], zg = sb[2][hd], zo = sb[3][hd];
            #pragma unroll
            for (int w = 0; w < 8; w++) {
                zf = fmaf(sWT[0][w][hd], zz[0][w], zf);
                zi = fmaf(sWT[1][w][hd], zz[1][w], zi);
                zg = fmaf(sWT[2][w][hd], zz[2][w], zg);
                zo = fmaf(sWT[3][w][hd], zz[3][w], zo);
            }
            float f  = 1.f / (1.f + expf(-zf));
            float ii = 1.f / (1.f + expf(-zi));
            float gg = tanhf(zg);
            float oo = 1.f / (1.f + expf(-zo));
            float cn = fmaf(f, cst[hd], ii * gg);
            float hn = oo * tanhf(cn);
            out[(t * BATCH + b) * HID + hd] = hn;
            cst[hd] = cn;
            comb[128 + hd] = hn;
        }
        __syncthreads();
    }

    // final hx, cx (packed after outputs: [SEQ,B,H] then hx[B,H] then cx[B,H])
    out[SEQ * BATCH * HID + b * HID + tid]               = comb[128 + tid];
    out[SEQ * BATCH * HID + BATCH * HID + b * HID + tid] = cst[tid];
}

extern "C" void kernel_launch(void* const* d_in, const int* in_sizes, int n_in,
                              void* d_out, int out_size) {
    const float* inputs = (const float*)d_in[0];
    const float* Wq  = (const float*)d_in[1];
    const float* bq  = (const float*)d_in[2];
    const float* pf  = (const float*)d_in[3];
    const float* pi_ = (const float*)d_in[4];
    const float* pg  = (const float*)d_in[5];
    const float* po  = (const float*)d_in[6];
    const float* Wf  = (const float*)d_in[7];
    const float* bf  = (const float*)d_in[8];
    const float* Wi  = (const float*)d_in[9];
    const float* bi  = (const float*)d_in[10];
    const float* Wg  = (const float*)d_in[11];
    const float* bg  = (const float*)d_in[12];
    const float* Wo  = (const float*)d_in[13];
    const float* bo  = (const float*)d_in[14];

    qlstm_kernel<<<BATCH, 128>>>(inputs, Wq, bq, pf, pi_, pg, po,
                                 Wf, bf, Wi, bi, Wg, bg, Wo, bo,
                                 (float*)d_out);
}